// round 3
// baseline (speedup 1.0000x reference)
#include <cuda_runtime.h>
#include <cuda_bf16.h>
#include <math.h>

// ResonanceRotaryEmbedding:
//   inputs : x [B,H,L,DIM] f32 (UNUSED except dtype), position_ids [B,L] i32,
//            r_inv_freq [D2] f32, r_wavelengths [D2] f32
//   outputs: cos [B,L,DIM] f32, sin [B,L,DIM] f32  (concatenated in d_out)
// DIM = 128, D2 = 64 fixed by the problem. B=2, L=8192.

__device__ int g_seq_len;

// Single-block max reduce over position_ids, vectorized int4.
__global__ __launch_bounds__(1024) void seqlen_reduce_kernel(const int* __restrict__ pos, int n) {
    const int tid = threadIdx.x;
    int m = -2147483647;
    const int n4 = n >> 2;
    const int4* p4 = reinterpret_cast<const int4*>(pos);
    for (int i = tid; i < n4; i += 1024) {
        int4 v = p4[i];
        m = max(m, max(max(v.x, v.y), max(v.z, v.w)));
    }
    // tail (n not multiple of 4)
    for (int i = (n4 << 2) + tid; i < n; i += 1024) m = max(m, pos[i]);

    #pragma unroll
    for (int o = 16; o > 0; o >>= 1)
        m = max(m, __shfl_xor_sync(0xFFFFFFFFu, m, o));
    __shared__ int smax[32];
    if ((tid & 31) == 0) smax[tid >> 5] = m;
    __syncthreads();
    if (tid < 32) {
        m = smax[tid];
        #pragma unroll
        for (int o = 16; o > 0; o >>= 1)
            m = max(m, __shfl_xor_sync(0xFFFFFFFFu, m, o));
        if (tid == 0) g_seq_len = m + 1;
    }
}

// One warp per (b,l) position. lane handles d = 2*lane, 2*lane+1.
// Writes cos row [128] and sin row [128] with float2 stores (fully coalesced).
__global__ __launch_bounds__(256) void resonance_rope_kernel(
    const int*   __restrict__ pos,        // [B*L]
    const float* __restrict__ r_inv_freq, // [64]
    const float* __restrict__ r_wl,       // [64]
    float*       __restrict__ cos_out,    // [B*L, 128]
    float*       __restrict__ sin_out,    // [B*L, 128]
    int L, int nPos)
{
    __shared__ float s_if[64];
    __shared__ int   s_w[64];
    int tid = threadIdx.x;
    if (tid < 64) {
        s_if[tid] = r_inv_freq[tid];
        s_w[tid]  = (int)r_wl[tid];   // wavelengths are exact integers stored as f32
    }
    __syncthreads();

    const int seq_len = g_seq_len;
    const int warp = tid >> 5;
    const int lane = tid & 31;
    const int posIdx = blockIdx.x * 8 + warp;     // linear (b*L + l)
    if (posIdx >= nPos) return;

    const int b = posIdx / L;
    const int l = posIdx - b * L;
    const int d0 = lane * 2;

    float c[2], s[2];
    #pragma unroll
    for (int k = 0; k < 2; k++) {
        const int d = d0 + k;
        const int w = s_w[d];
        const int idx = (w <= seq_len) ? (l % w) : l;
        const float p = (float)__ldg(&pos[b * L + idx]);
        sincosf(p * s_if[d], &s[k], &c[k]);
    }

    const size_t base = (size_t)posIdx * 128;
    const float2 cv = make_float2(c[0], c[1]);
    const float2 sv = make_float2(s[0], s[1]);
    *reinterpret_cast<float2*>(cos_out + base + d0)      = cv;   // concat copy 1
    *reinterpret_cast<float2*>(cos_out + base + 64 + d0) = cv;   // concat copy 2
    *reinterpret_cast<float2*>(sin_out + base + d0)      = sv;
    *reinterpret_cast<float2*>(sin_out + base + 64 + d0) = sv;
}

extern "C" void kernel_launch(void* const* d_in, const int* in_sizes, int n_in,
                              void* d_out, int out_size) {
    // metadata order: x, position_ids, r_inv_freq, r_wavelengths
    const int*   pos  = (const int*)  d_in[1];
    const float* invf = (const float*)d_in[2];
    const float* wl   = (const float*)d_in[3];

    const int nPos = in_sizes[1];          // B * L
    const int L = 8192;                    // known problem shape (B=2, L=8192)

    float* cos_out = (float*)d_out;
    float* sin_out = (float*)d_out + (size_t)nPos * 128;

    seqlen_reduce_kernel<<<1, 1024>>>(pos, nPos);

    const int blocks = (nPos + 7) / 8;     // 8 warps (positions) per block
    resonance_rope_kernel<<<blocks, 256>>>(pos, invf, wl, cos_out, sin_out, L, nPos);
}

// round 4
// speedup vs baseline: 1.0798x; 1.0798x over previous
#include <cuda_runtime.h>
#include <cuda_bf16.h>
#include <math.h>

// ResonanceRotaryEmbedding:
//   inputs : x [B,H,L,DIM] f32 (unused), position_ids [B,L] i32,
//            r_inv_freq [64] f32, r_wavelengths [64] f32
//   outputs: cos [B,L,128] f32, sin [B,L,128] f32 concatenated in d_out.
// DIM=128, D2=64, B=2, L=8192.

__device__ int g_seq_len;

// Single-block max reduce over position_ids, vectorized int4.
__global__ __launch_bounds__(1024) void seqlen_reduce_kernel(const int* __restrict__ pos, int n) {
    const int tid = threadIdx.x;
    int m = -2147483647;
    const int n4 = n >> 2;
    const int4* p4 = reinterpret_cast<const int4*>(pos);
    for (int i = tid; i < n4; i += 1024) {
        int4 v = p4[i];
        m = max(m, max(max(v.x, v.y), max(v.z, v.w)));
    }
    for (int i = (n4 << 2) + tid; i < n; i += 1024) m = max(m, pos[i]);

    #pragma unroll
    for (int o = 16; o > 0; o >>= 1)
        m = max(m, __shfl_xor_sync(0xFFFFFFFFu, m, o));
    __shared__ int smax[32];
    if ((tid & 31) == 0) smax[tid >> 5] = m;
    __syncthreads();
    if (tid < 32) {
        m = smax[tid];
        #pragma unroll
        for (int o = 16; o > 0; o >>= 1)
            m = max(m, __shfl_xor_sync(0xFFFFFFFFu, m, o));
        if (tid == 0) g_seq_len = m + 1;
    }
}

// Fast FMA-pipe sincos: Cody-Waite 2-term range reduction (exact via FMA) +
// degree-7/8 minimax polys + quadrant fixup. ~25 SASS instr, NO MUFU
// (MUFU.SIN at rt 8/SMSP would be the throughput bottleneck at this op count).
// Valid to ~1e-7 abs for |x| up to ~1e4 (here |x| < 2*pi typically).
__device__ __forceinline__ void fast_sincosf(float x, float* sp, float* cp) {
    const float INV_PIO2 = 0.636619772f;
    const float PIO2_HI  = 1.57079637e+0f;   // fp32(pi/2)
    const float PIO2_LO  = -4.37113883e-8f;  // pi/2 - PIO2_HI
    float qf = rintf(x * INV_PIO2);
    int   iq = (int)qf;
    float r  = fmaf(-qf, PIO2_HI, x);
    r        = fmaf(-qf, PIO2_LO, r);
    float r2 = r * r;
    // sin(r), |r| <= pi/4
    float s = fmaf(2.7525562e-6f, r2, -1.9840874e-4f);
    s = fmaf(s, r2, 8.3333310e-3f);
    s = fmaf(s, r2, -1.6666667e-1f);
    s = fmaf(s * r2, r, r);
    // cos(r)
    float c = fmaf(2.4760495e-5f, r2, -1.3888378e-3f);
    c = fmaf(c, r2, 4.1666638e-2f);
    c = fmaf(c, r2, -0.5f);
    c = fmaf(c, r2, 1.0f);
    // quadrant: sin(x) = {s, c, -s, -c}[iq&3], cos(x) = {c, -s, -c, s}[iq&3]
    float sv = (iq & 1) ? c : s;
    float cv = (iq & 1) ? s : c;
    if (iq & 2)       sv = -sv;
    if ((iq + 1) & 2) cv = -cv;
    *sp = sv;
    *cp = cv;
}

// One warp per (b,l) row; lane owns d = 2*lane, 2*lane+1.
__global__ __launch_bounds__(256) void resonance_rope_kernel(
    const int*   __restrict__ pos,        // [B*L]
    const float* __restrict__ r_inv_freq, // [64]
    const float* __restrict__ r_wl,       // [64]
    float*       __restrict__ cos_out,    // [B*L, 128]
    float*       __restrict__ sin_out,    // [B*L, 128]
    int L, int nPos)
{
    __shared__ float s_if[64];
    __shared__ int   s_w[64];
    __shared__ float s_rw[64];            // 1/w for div-free modulo
    int tid = threadIdx.x;
    if (tid < 64) {
        float wf = r_wl[tid];
        s_if[tid] = r_inv_freq[tid];
        s_w[tid]  = (int)wf;              // wavelengths are exact small integers in f32
        s_rw[tid] = 1.0f / wf;
    }
    __syncthreads();

    const int seq_len = g_seq_len;
    const int warp = tid >> 5;
    const int lane = tid & 31;
    const int posIdx = blockIdx.x * 8 + warp;     // linear b*L + l
    if (posIdx >= nPos) return;

    const int b = posIdx / L;
    const int l = posIdx - b * L;
    const int rowBase = b * L;
    const int d0 = lane * 2;
    const float lf = (float)l;

    float c[2], s[2];
    #pragma unroll
    for (int k = 0; k < 2; k++) {
        const int d = d0 + k;
        const int w = s_w[d];
        // idx = l % w via float reciprocal + exact fixup (q off by at most +-1)
        int q   = (int)(lf * s_rw[d]);
        int im  = l - q * w;
        if (im < 0)       im += w;
        else if (im >= w) im -= w;
        const int idx = (w <= seq_len) ? im : l;
        const float p = (float)__ldg(&pos[rowBase + idx]);
        fast_sincosf(p * s_if[d], &s[k], &c[k]);
    }

    const size_t base = (size_t)posIdx * 128;
    const float2 cv = make_float2(c[0], c[1]);
    const float2 sv = make_float2(s[0], s[1]);
    *reinterpret_cast<float2*>(cos_out + base + d0)      = cv;   // concat half 1
    *reinterpret_cast<float2*>(cos_out + base + 64 + d0) = cv;   // concat half 2
    *reinterpret_cast<float2*>(sin_out + base + d0)      = sv;
    *reinterpret_cast<float2*>(sin_out + base + 64 + d0) = sv;
}

extern "C" void kernel_launch(void* const* d_in, const int* in_sizes, int n_in,
                              void* d_out, int out_size) {
    // metadata order: x, position_ids, r_inv_freq, r_wavelengths
    const int*   pos  = (const int*)  d_in[1];
    const float* invf = (const float*)d_in[2];
    const float* wl   = (const float*)d_in[3];

    const int nPos = in_sizes[1];          // B * L
    const int L = 8192;                    // known problem shape (B=2, L=8192)

    float* cos_out = (float*)d_out;
    float* sin_out = (float*)d_out + (size_t)nPos * 128;

    seqlen_reduce_kernel<<<1, 1024>>>(pos, nPos);

    const int blocks = (nPos + 7) / 8;     // 8 warps (rows) per block
    resonance_rope_kernel<<<blocks, 256>>>(pos, invf, wl, cos_out, sin_out, L, nPos);
}